// round 16
// baseline (speedup 1.0000x reference)
#include <cuda_runtime.h>
#include <cuda_bf16.h>
#include <cstdint>

// out[b,o,p] = sum_c refine_w[o,c]*x[b,c,p] + refine_b[o]
// (rest of reference graph is dead: x_back == x exactly, _dead unused)
// B=8, C=64, HW=65536, fp32.
//
// R16: mma.sync bf16 split-precision (validated 4e-6). vs R15:
//  - M=32 pixels/warp (2 A-tiles share each B-fragment) -> LDS/pixel halved
//  - B fragments stored as uint2 (b0,b1) pairs -> LDS.64, conflict-free via
//    slot ^ ((o&3)<<2) swizzle on the 16 x 8B banks.

#define CC   64
#define HW   65536
#define BP   256          // pixels per CTA (8 warps x 32)
#define NTHR 256

static __device__ __forceinline__ void bf16_split2(float a, float b,
                                                   uint32_t& hi, uint32_t& lo)
{
    __nv_bfloat16 ha = __float2bfloat16_rn(a);
    __nv_bfloat16 hb = __float2bfloat16_rn(b);
    float ra = a - __bfloat162float(ha);
    float rb = b - __bfloat162float(hb);
    __nv_bfloat162 H; H.x = ha; H.y = hb;
    __nv_bfloat162 L = __floats2bfloat162_rn(ra, rb);
    hi = *reinterpret_cast<uint32_t*>(&H);
    lo = *reinterpret_cast<uint32_t*>(&L);
}

static __device__ __forceinline__ void mma16816(float* d, const uint32_t* a,
                                                uint32_t b0, uint32_t b1)
{
    asm volatile(
        "mma.sync.aligned.m16n8k16.row.col.f32.bf16.bf16.f32 "
        "{%0,%1,%2,%3}, {%4,%5,%6,%7}, {%8,%9}, {%0,%1,%2,%3};"
        : "+f"(d[0]), "+f"(d[1]), "+f"(d[2]), "+f"(d[3])
        : "r"(a[0]), "r"(a[1]), "r"(a[2]), "r"(a[3]), "r"(b0), "r"(b1));
}

__global__ __launch_bounds__(NTHR) void conv1x1_mma_kernel(
    const float* __restrict__ x,
    const float* __restrict__ w,      // [64][64] (o,c)
    const float* __restrict__ bias,   // [64]
    float* __restrict__ out)
{
    // B fragments: per (o, slot) a uint2 = (b_k0, b_k1); slot = ks*4+tig,
    // XOR-swizzled with (o&3)<<2. hi and lo splits, 8 KB each.
    __shared__ uint2 sh_h[CC * 16];
    __shared__ uint2 sh_l[CC * 16];

    const int t    = threadIdx.x;
    const int wid  = t >> 5;
    const int lane = t & 31;
    const int gid  = lane >> 2;     // pixel row within tile / B col
    const int tig  = lane & 3;      // k-pair selector
    const int b    = blockIdx.y;
    const int p0   = blockIdx.x * BP + wid * 32;   // this warp's 32 pixels

    // ---- build weight smem: 1024 uint2 per array, 4 per thread ----
#pragma unroll
    for (int k = 0; k < 4; k++) {
        int i    = t + k * NTHR;        // entry = o*16 + slot
        int o    = i >> 4;
        int slot = i & 15;
        int ks   = slot >> 2;
        int tg   = slot & 3;
        int cp0  = ks * 8 + tg;         // b0 covers channels 2cp0, 2cp0+1
        int cp1  = cp0 + 4;             // b1 covers channels 2cp1, 2cp1+1
        uint32_t h0, l0, h1, l1;
        bf16_split2(__ldg(w + o * CC + 2 * cp0), __ldg(w + o * CC + 2 * cp0 + 1), h0, l0);
        bf16_split2(__ldg(w + o * CC + 2 * cp1), __ldg(w + o * CC + 2 * cp1 + 1), h1, l1);
        int si = o * 16 + (slot ^ ((o & 3) << 2));
        sh_h[si] = make_uint2(h0, h1);
        sh_l[si] = make_uint2(l0, l1);
    }
    __syncthreads();

    // d[nt][m][4]: nt = 8-output tile, m = pixel tile (0: p0.., 1: p0+16..)
    float d[8][2][4];
#pragma unroll
    for (int nt = 0; nt < 8; nt++)
#pragma unroll
        for (int m = 0; m < 2; m++)
#pragma unroll
            for (int q = 0; q < 4; q++) d[nt][m][q] = 0.f;

    const float* xg = x + (size_t)b * CC * HW + p0;

#pragma unroll
    for (int ks = 0; ks < 4; ks++) {
        const int ca = ks * 16 + 2 * tig;
        const int cb = ca + 8;

        uint32_t ah[2][4], al[2][4];
#pragma unroll
        for (int m = 0; m < 2; m++) {
            const float* xm = xg + m * 16;
            float v0 = __ldg(xm + (size_t)ca       * HW + gid);
            float v1 = __ldg(xm + (size_t)(ca + 1) * HW + gid);
            float v2 = __ldg(xm + (size_t)ca       * HW + gid + 8);
            float v3 = __ldg(xm + (size_t)(ca + 1) * HW + gid + 8);
            float v4 = __ldg(xm + (size_t)cb       * HW + gid);
            float v5 = __ldg(xm + (size_t)(cb + 1) * HW + gid);
            float v6 = __ldg(xm + (size_t)cb       * HW + gid + 8);
            float v7 = __ldg(xm + (size_t)(cb + 1) * HW + gid + 8);
            bf16_split2(v0, v1, ah[m][0], al[m][0]);   // (row gid,   ca)
            bf16_split2(v2, v3, ah[m][1], al[m][1]);   // (row gid+8, ca)
            bf16_split2(v4, v5, ah[m][2], al[m][2]);   // (row gid,   cb)
            bf16_split2(v6, v7, ah[m][3], al[m][3]);   // (row gid+8, cb)
        }

        const int slot = (ks * 4 + tig) ^ ((gid & 3) << 2);
#pragma unroll
        for (int nt = 0; nt < 8; nt++) {
            const int o = nt * 8 + gid;
            uint2 bh = sh_h[o * 16 + slot];
            uint2 bl = sh_l[o * 16 + slot];
#pragma unroll
            for (int m = 0; m < 2; m++) {
                mma16816(d[nt][m], ah[m], bh.x, bh.y);   // hh
                mma16816(d[nt][m], ah[m], bl.x, bl.y);   // hi(x)*lo(w)
                mma16816(d[nt][m], al[m], bh.x, bh.y);   // lo(x)*hi(w)
            }
        }
    }

    // ---- epilogue: + bias, sector-coalesced STG.32 ----
    float* og = out + (size_t)b * CC * HW + p0;
#pragma unroll
    for (int nt = 0; nt < 8; nt++) {
        const int o0 = nt * 8 + 2 * tig;
        float bo0 = __ldg(bias + o0);
        float bo1 = __ldg(bias + o0 + 1);
#pragma unroll
        for (int m = 0; m < 2; m++) {
            float* om = og + m * 16;
            om[(size_t)o0       * HW + gid]     = d[nt][m][0] + bo0;
            om[(size_t)(o0 + 1) * HW + gid]     = d[nt][m][1] + bo1;
            om[(size_t)o0       * HW + gid + 8] = d[nt][m][2] + bo0;
            om[(size_t)(o0 + 1) * HW + gid + 8] = d[nt][m][3] + bo1;
        }
    }
}

extern "C" void kernel_launch(void* const* d_in, const int* in_sizes, int n_in,
                              void* d_out, int out_size)
{
    (void)in_sizes; (void)n_in; (void)out_size;
    const float* x    = (const float*)d_in[0];   // x
    const float* w    = (const float*)d_in[11];  // refine_w
    const float* bias = (const float*)d_in[12];  // refine_b
    float* out = (float*)d_out;

    dim3 grid(HW / BP, 8);   // 256 pixel tiles x 8 batches
    conv1x1_mma_kernel<<<grid, NTHR>>>(x, w, bias, out);
}